// round 1
// baseline (speedup 1.0000x reference)
#include <cuda_runtime.h>

#define NN 100000
#define NE 800000

// scatter-add scratch (allocation-free rule: __device__ global)
__device__ float g_agg[NN * 32];

typedef unsigned long long u64;

__device__ __forceinline__ u64 pack2(float x) {
    u64 r;
    asm("mov.b64 %0, {%1, %1};" : "=l"(r) : "f"(x));
    return r;
}
__device__ __forceinline__ void unpack2(u64 v, float& a, float& b) {
    asm("mov.b64 {%0, %1}, %2;" : "=f"(a), "=f"(b) : "l"(v));
}
// packed fp32x2 FMA: d = a*b + d  (2x FFMA throughput on sm_103a)
__device__ __forceinline__ void ffma2(u64& d, u64 a, u64 b) {
    asm("fma.rn.f32x2 %0, %1, %2, %0;" : "+l"(d) : "l"(a), "l"(b));
}

// rank-1 update for 2 edges, 64 packed outputs (32 u64 accumulators each).
// One ulonglong2 smem load (4 weights) feeds 4 FFMA2 -> LDS:FMA = 1:4.
__device__ __forceinline__ void rank1_2(float xaf, float xbf, const float* wrow,
                                        u64* a0, u64* a1) {
    u64 xa = pack2(xaf), xb = pack2(xbf);
    const ulonglong2* wr = (const ulonglong2*)wrow;
#pragma unroll
    for (int j = 0; j < 16; j++) {
        ulonglong2 w = wr[j];
        ffma2(a0[2 * j],     xa, w.x);
        ffma2(a0[2 * j + 1], xa, w.y);
        ffma2(a1[2 * j],     xb, w.x);
        ffma2(a1[2 * j + 1], xb, w.y);
    }
}

// rank-1 update for 2 edges, 32 outputs (16 u64 accumulators each) — layer 2.
__device__ __forceinline__ void rank1_2h(float xaf, float xbf, const float* wrow,
                                         u64* a0, u64* a1) {
    u64 xa = pack2(xaf), xb = pack2(xbf);
    const ulonglong2* wr = (const ulonglong2*)wrow;
#pragma unroll
    for (int j = 0; j < 8; j++) {
        ulonglong2 w = wr[j];
        ffma2(a0[2 * j],     xa, w.x);
        ffma2(a0[2 * j + 1], xa, w.y);
        ffma2(a1[2 * j],     xb, w.x);
        ffma2(a1[2 * j + 1], xb, w.y);
    }
}

// Accumulate one 32-wide input segment (for 2 edges) through a 32x64 slice of W0.
__device__ __forceinline__ void seg_accum2(const float* __restrict__ s0,
                                           const float* __restrict__ s1,
                                           const float* __restrict__ wseg,
                                           u64* acc0, u64* acc1) {
    const float4* p0 = (const float4*)s0;
    const float4* p1 = (const float4*)s1;
    float4 a = p0[0], b = p1[0];
#pragma unroll 1
    for (int i = 0; i < 8; i++) {
        int in = (i < 7) ? (i + 1) : 7;   // prefetch next chunk (clamped, safe)
        float4 an = p0[in];
        float4 bn = p1[in];
        const float* w = wseg + i * 256;  // 4 rows of 64
        rank1_2(a.x, b.x, w,       acc0, acc1);
        rank1_2(a.y, b.y, w + 64,  acc0, acc1);
        rank1_2(a.z, b.z, w + 128, acc0, acc1);
        rank1_2(a.w, b.w, w + 192, acc0, acc1);
        a = an; b = bn;
    }
}

__device__ __forceinline__ void epilogue(const u64* acc3, const float* __restrict__ h_d,
                                         int sidx, int ridx) {
    const float4* pi = (const float4*)(h_d + (size_t)sidx * 32);
    const float4* pj = (const float4*)(h_d + (size_t)ridx * 32);
    float* out = g_agg + (size_t)ridx * 32;
#pragma unroll
    for (int q = 0; q < 8; q++) {
        float4 a = pj[q], b = pi[q];
        float d0 = a.x - b.x, d1 = a.y - b.y, d2 = a.z - b.z, d3 = a.w - b.w;
        float lo, hi;
        unpack2(acc3[2 * q], lo, hi);
        atomicAdd(out + 4 * q + 0, fmaxf(lo, 0.f) * d0);
        atomicAdd(out + 4 * q + 1, fmaxf(hi, 0.f) * d1);
        unpack2(acc3[2 * q + 1], lo, hi);
        atomicAdd(out + 4 * q + 2, fmaxf(lo, 0.f) * d2);
        atomicAdd(out + 4 * q + 3, fmaxf(hi, 0.f) * d3);
    }
}

// smem layout (floats):
//   s_w0: [0, 10240)     160x64
//   s_w1: [10240, 14336)  64x64
//   s_w2: [14336, 16384)  64x32
//   s_b0: [16384, 16448)
//   s_b1: [16448, 16512)
//   s_b2: [16512, 16544)
//   s_h0: [16544, 49312)  64 rows x (2 slots x 256 threads)
#define SMEM_FLOATS 49312
#define SMEM_BYTES  (SMEM_FLOATS * 4)

__global__ void __launch_bounds__(256, 1)
edge_kernel(const float* __restrict__ h_d, const float* __restrict__ h_s,
            const float* __restrict__ ef, const int* __restrict__ si,
            const int* __restrict__ ri,
            const float* __restrict__ w0, const float* __restrict__ b0,
            const float* __restrict__ w1, const float* __restrict__ b1,
            const float* __restrict__ w2, const float* __restrict__ b2) {
    extern __shared__ float smem[];
    float* s_w0 = smem;
    float* s_w1 = smem + 10240;
    float* s_w2 = smem + 14336;
    float* s_b0 = smem + 16384;
    float* s_b1 = smem + 16448;
    float* s_b2 = smem + 16512;
    float* s_h0 = smem + 16544;

    const int tid = threadIdx.x;

    // stage all weights once per (persistent) CTA
    {
        float4* d4 = (float4*)s_w0;
        const float4* s4 = (const float4*)w0;
        for (int i = tid; i < 2560; i += 256) d4[i] = s4[i];
        d4 = (float4*)s_w1; s4 = (const float4*)w1;
        for (int i = tid; i < 1024; i += 256) d4[i] = s4[i];
        d4 = (float4*)s_w2; s4 = (const float4*)w2;
        for (int i = tid; i < 512; i += 256) d4[i] = s4[i];
        if (tid < 64) { s_b0[tid] = b0[tid]; s_b1[tid] = b1[tid]; }
        if (tid < 32) s_b2[tid] = b2[tid];
    }
    __syncthreads();

    const int stride = gridDim.x * 512;
    for (int base = blockIdx.x * 512; base < NE; base += stride) {
        int e0 = base + tid;
        int e1 = base + 256 + tid;
        bool v0 = e0 < NE, v1 = e1 < NE;
        int ee0 = v0 ? e0 : (NE - 1);
        int ee1 = v1 ? e1 : (NE - 1);
        int s0i = si[ee0], r0i = ri[ee0];
        int s1i = si[ee1], r1i = ri[ee1];

        // ---------- layer 0 ----------
        u64 acc0[32], acc1[32];
        {
            const ulonglong2* bp = (const ulonglong2*)s_b0;
#pragma unroll
            for (int j = 0; j < 16; j++) {
                ulonglong2 t = bp[j];
                acc0[2 * j] = t.x; acc0[2 * j + 1] = t.y;
                acc1[2 * j] = t.x; acc1[2 * j + 1] = t.y;
            }
        }
        seg_accum2(h_s + (size_t)s0i * 32, h_s + (size_t)s1i * 32, s_w0,        acc0, acc1);
        seg_accum2(h_s + (size_t)r0i * 32, h_s + (size_t)r1i * 32, s_w0 + 2048, acc0, acc1);
        seg_accum2(h_d + (size_t)s0i * 32, h_d + (size_t)s1i * 32, s_w0 + 4096, acc0, acc1);
        seg_accum2(h_d + (size_t)r0i * 32, h_d + (size_t)r1i * 32, s_w0 + 6144, acc0, acc1);
        seg_accum2(ef + (size_t)ee0 * 32,  ef + (size_t)ee1 * 32,  s_w0 + 8192, acc0, acc1);

        // relu -> stage h0 in smem (per-thread private columns, no sync needed)
#pragma unroll
        for (int j = 0; j < 32; j++) {
            float a, b;
            unpack2(acc0[j], a, b);
            s_h0[(2 * j) * 512 + tid]           = fmaxf(a, 0.f);
            s_h0[(2 * j + 1) * 512 + tid]       = fmaxf(b, 0.f);
            unpack2(acc1[j], a, b);
            s_h0[(2 * j) * 512 + 256 + tid]     = fmaxf(a, 0.f);
            s_h0[(2 * j + 1) * 512 + 256 + tid] = fmaxf(b, 0.f);
        }

        // ---------- layer 1 ----------
        u64 acc2a[32], acc2b[32];
        {
            const ulonglong2* bp = (const ulonglong2*)s_b1;
#pragma unroll
            for (int j = 0; j < 16; j++) {
                ulonglong2 t = bp[j];
                acc2a[2 * j] = t.x; acc2a[2 * j + 1] = t.y;
                acc2b[2 * j] = t.x; acc2b[2 * j + 1] = t.y;
            }
        }
#pragma unroll 2
        for (int k = 0; k < 64; k++) {
            float xa = s_h0[k * 512 + tid];
            float xb = s_h0[k * 512 + 256 + tid];
            rank1_2(xa, xb, s_w1 + k * 64, acc2a, acc2b);
        }
        // relu -> restage h1 (reads above all precede these writes; own column only)
#pragma unroll
        for (int j = 0; j < 32; j++) {
            float a, b;
            unpack2(acc2a[j], a, b);
            s_h0[(2 * j) * 512 + tid]           = fmaxf(a, 0.f);
            s_h0[(2 * j + 1) * 512 + tid]       = fmaxf(b, 0.f);
            unpack2(acc2b[j], a, b);
            s_h0[(2 * j) * 512 + 256 + tid]     = fmaxf(a, 0.f);
            s_h0[(2 * j + 1) * 512 + 256 + tid] = fmaxf(b, 0.f);
        }

        // ---------- layer 2 ----------
        u64 acc3a[16], acc3b[16];
        {
            const ulonglong2* bp = (const ulonglong2*)s_b2;
#pragma unroll
            for (int j = 0; j < 8; j++) {
                ulonglong2 t = bp[j];
                acc3a[2 * j] = t.x; acc3a[2 * j + 1] = t.y;
                acc3b[2 * j] = t.x; acc3b[2 * j + 1] = t.y;
            }
        }
#pragma unroll 2
        for (int k = 0; k < 64; k++) {
            float xa = s_h0[k * 512 + tid];
            float xb = s_h0[k * 512 + 256 + tid];
            rank1_2h(xa, xb, s_w2 + k * 32, acc3a, acc3b);
        }

        // ---------- epilogue: relu(psi) * (h_dj - h_di), scatter-add ----------
        if (v0) epilogue(acc3a, h_d, s0i, r0i);
        if (v1) epilogue(acc3b, h_d, s1i, r1i);
    }
}

__global__ void zero_kernel() {
    int i = blockIdx.x * blockDim.x + threadIdx.x;
    if (i < NN * 32 / 4) ((float4*)g_agg)[i] = make_float4(0.f, 0.f, 0.f, 0.f);
}

// out[n] = h_d_prev[n] + agg[n] @ W   (one warp per node)
__global__ void final_kernel(const float* __restrict__ h_d, const float* __restrict__ W,
                             float* __restrict__ out) {
    __shared__ float sW[1024];
    int tid = threadIdx.x;
    for (int i = tid; i < 1024; i += 256) sW[i] = W[i];
    __syncthreads();
    int n = blockIdx.x * 8 + (tid >> 5);
    if (n >= NN) return;
    int lane = tid & 31;
    float a = g_agg[(size_t)n * 32 + lane];
    float acc = h_d[(size_t)n * 32 + lane];
#pragma unroll
    for (int k = 0; k < 32; k++) {
        float ak = __shfl_sync(0xffffffffu, a, k);
        acc = fmaf(ak, sW[k * 32 + lane], acc);
    }
    out[(size_t)n * 32 + lane] = acc;
}

extern "C" void kernel_launch(void* const* d_in, const int* in_sizes, int n_in,
                              void* d_out, int out_size) {
    const float* h_d = (const float*)d_in[0];
    const float* h_s = (const float*)d_in[1];
    const float* ef  = (const float*)d_in[2];
    const int*   si  = (const int*)d_in[3];
    const int*   ri  = (const int*)d_in[4];
    const float* w0  = (const float*)d_in[5];
    const float* b0  = (const float*)d_in[6];
    const float* w1  = (const float*)d_in[7];
    const float* b1  = (const float*)d_in[8];
    const float* w2  = (const float*)d_in[9];
    const float* b2  = (const float*)d_in[10];
    const float* W   = (const float*)d_in[11];
    float* out = (float*)d_out;

    cudaFuncSetAttribute(edge_kernel, cudaFuncAttributeMaxDynamicSharedMemorySize,
                         SMEM_BYTES);

    zero_kernel<<<(NN * 32 / 4 + 255) / 256, 256>>>();
    edge_kernel<<<148, 256, SMEM_BYTES>>>(h_d, h_s, ef, si, ri,
                                          w0, b0, w1, b1, w2, b2);
    final_kernel<<<(NN + 7) / 8, 256>>>(h_d, W, out);
}

// round 2
// speedup vs baseline: 1.2141x; 1.2141x over previous
#include <cuda_runtime.h>

#define NN 100000
#define NE 800000

// scratch (allocation-free rule: __device__ globals)
__device__ float g_agg[NN * 32];
__device__ float g_P[NN * 64];   // h_s@W0a + h_d@W0c
__device__ float g_Q[NN * 64];   // h_s@W0b + h_d@W0d + b0

typedef unsigned long long u64;

__device__ __forceinline__ u64 pack2(float x) {
    u64 r;
    asm("mov.b64 %0, {%1, %1};" : "=l"(r) : "f"(x));
    return r;
}
__device__ __forceinline__ void unpack2(u64 v, float& a, float& b) {
    asm("mov.b64 {%0, %1}, %2;" : "=f"(a), "=f"(b) : "l"(v));
}
// packed fp32x2 FMA: d = a*b + d
__device__ __forceinline__ void ffma2(u64& d, u64 a, u64 b) {
    asm("fma.rn.f32x2 %0, %1, %2, %0;" : "+l"(d) : "l"(a), "l"(b));
}
__device__ __forceinline__ u64 add2(u64 a, u64 b) {
    u64 r;
    asm("add.rn.f32x2 %0, %1, %2;" : "=l"(r) : "l"(a), "l"(b));
    return r;
}

// rank-1 update, 1 edge, 64 outputs (32 u64 acc)
__device__ __forceinline__ void rank1_1(float xf, const float* wrow, u64* a0) {
    u64 xa = pack2(xf);
    const ulonglong2* wr = (const ulonglong2*)wrow;
#pragma unroll
    for (int j = 0; j < 16; j++) {
        ulonglong2 w = wr[j];
        ffma2(a0[2 * j],     xa, w.x);
        ffma2(a0[2 * j + 1], xa, w.y);
    }
}

// rank-1 update, 2 edges, 64 outputs each
__device__ __forceinline__ void rank1_2(float xaf, float xbf, const float* wrow,
                                        u64* a0, u64* a1) {
    u64 xa = pack2(xaf), xb = pack2(xbf);
    const ulonglong2* wr = (const ulonglong2*)wrow;
#pragma unroll
    for (int j = 0; j < 16; j++) {
        ulonglong2 w = wr[j];
        ffma2(a0[2 * j],     xa, w.x);
        ffma2(a0[2 * j + 1], xa, w.y);
        ffma2(a1[2 * j],     xb, w.x);
        ffma2(a1[2 * j + 1], xb, w.y);
    }
}

// rank-1 update, 2 edges, 32 outputs each (layer 2)
__device__ __forceinline__ void rank1_2h(float xaf, float xbf, const float* wrow,
                                         u64* a0, u64* a1) {
    u64 xa = pack2(xaf), xb = pack2(xbf);
    const ulonglong2* wr = (const ulonglong2*)wrow;
#pragma unroll
    for (int j = 0; j < 8; j++) {
        ulonglong2 w = wr[j];
        ffma2(a0[2 * j],     xa, w.x);
        ffma2(a0[2 * j + 1], xa, w.y);
        ffma2(a1[2 * j],     xb, w.x);
        ffma2(a1[2 * j + 1], xb, w.y);
    }
}

// one 32-wide input segment (2 edges) through a 32x64 weight slice
__device__ __forceinline__ void seg_accum2(const float* __restrict__ s0,
                                           const float* __restrict__ s1,
                                           const float* __restrict__ wseg,
                                           u64* acc0, u64* acc1) {
    const float4* p0 = (const float4*)s0;
    const float4* p1 = (const float4*)s1;
    float4 a = p0[0], b = p1[0];
#pragma unroll 1
    for (int i = 0; i < 8; i++) {
        int in = (i < 7) ? (i + 1) : 7;
        float4 an = p0[in];
        float4 bn = p1[in];
        const float* w = wseg + i * 256;
        rank1_2(a.x, b.x, w,       acc0, acc1);
        rank1_2(a.y, b.y, w + 64,  acc0, acc1);
        rank1_2(a.z, b.z, w + 128, acc0, acc1);
        rank1_2(a.w, b.w, w + 192, acc0, acc1);
        a = an; b = bn;
    }
}

__device__ __forceinline__ void epilogue(const u64* acc3, const float* __restrict__ h_d,
                                         int sidx, int ridx) {
    const float4* pi = (const float4*)(h_d + (size_t)sidx * 32);
    const float4* pj = (const float4*)(h_d + (size_t)ridx * 32);
    float* out = g_agg + (size_t)ridx * 32;
#pragma unroll
    for (int q = 0; q < 8; q++) {
        float4 a = pj[q], b = pi[q];
        float d0 = a.x - b.x, d1 = a.y - b.y, d2 = a.z - b.z, d3 = a.w - b.w;
        float lo, hi;
        unpack2(acc3[2 * q], lo, hi);
        atomicAdd(out + 4 * q + 0, fmaxf(lo, 0.f) * d0);
        atomicAdd(out + 4 * q + 1, fmaxf(hi, 0.f) * d1);
        unpack2(acc3[2 * q + 1], lo, hi);
        atomicAdd(out + 4 * q + 2, fmaxf(lo, 0.f) * d2);
        atomicAdd(out + 4 * q + 3, fmaxf(hi, 0.f) * d3);
    }
}

// ---------------- node precompute: P[n], Q[n] ----------------
__global__ void __launch_bounds__(256)
precompute_kernel(const float* __restrict__ h_s, const float* __restrict__ h_d,
                  const float* __restrict__ w0, const float* __restrict__ b0) {
    __shared__ float s_w0[128 * 64];   // W0 rows 0..127
    __shared__ float s_b0[64];
    const int tid = threadIdx.x;
    {
        float4* d4 = (float4*)s_w0;
        const float4* s4 = (const float4*)w0;
        for (int i = tid; i < 2048; i += 256) d4[i] = s4[i];
        if (tid < 64) s_b0[tid] = b0[tid];
    }
    __syncthreads();

    int n = blockIdx.x * 256 + tid;
    if (n >= NN) return;

    u64 P[32], Q[32];
    {
        const ulonglong2* bp = (const ulonglong2*)s_b0;
#pragma unroll
        for (int j = 0; j < 16; j++) {
            ulonglong2 t = bp[j];
            P[2 * j] = 0ull; P[2 * j + 1] = 0ull;
            Q[2 * j] = t.x;  Q[2 * j + 1] = t.y;
        }
    }
    const float4* xs = (const float4*)(h_s + (size_t)n * 32);
    const float4* xd = (const float4*)(h_d + (size_t)n * 32);
#pragma unroll 1
    for (int i = 0; i < 8; i++) {
        float4 a = xs[i];
        const float* wa = s_w0 + (4 * i) * 64;        // W0a rows
        const float* wb = s_w0 + (32 + 4 * i) * 64;   // W0b rows
        rank1_1(a.x, wa,       P); rank1_1(a.x, wb,       Q);
        rank1_1(a.y, wa + 64,  P); rank1_1(a.y, wb + 64,  Q);
        rank1_1(a.z, wa + 128, P); rank1_1(a.z, wb + 128, Q);
        rank1_1(a.w, wa + 192, P); rank1_1(a.w, wb + 192, Q);
    }
#pragma unroll 1
    for (int i = 0; i < 8; i++) {
        float4 a = xd[i];
        const float* wc = s_w0 + (64 + 4 * i) * 64;   // W0c rows
        const float* wd = s_w0 + (96 + 4 * i) * 64;   // W0d rows
        rank1_1(a.x, wc,       P); rank1_1(a.x, wd,       Q);
        rank1_1(a.y, wc + 64,  P); rank1_1(a.y, wd + 64,  Q);
        rank1_1(a.z, wc + 128, P); rank1_1(a.z, wd + 128, Q);
        rank1_1(a.w, wc + 192, P); rank1_1(a.w, wd + 192, Q);
    }
    ulonglong2* po = (ulonglong2*)(g_P + (size_t)n * 64);
    ulonglong2* qo = (ulonglong2*)(g_Q + (size_t)n * 64);
#pragma unroll
    for (int j = 0; j < 16; j++) {
        ulonglong2 t; t.x = P[2 * j]; t.y = P[2 * j + 1]; po[j] = t;
        ulonglong2 u; u.x = Q[2 * j]; u.y = Q[2 * j + 1]; qo[j] = u;
    }
}

// ---------------- edge kernel ----------------
// smem (floats): s_w0e [0,2048), s_w1 [2048,6144), s_w2 [6144,8192),
//                s_b1 [8192,8256), s_b2 [8256,8288), s_h0 [8288,41056)
#define SMEM_FLOATS 41056
#define SMEM_BYTES  (SMEM_FLOATS * 4)

__global__ void __launch_bounds__(256, 1)
edge_kernel(const float* __restrict__ h_d,
            const float* __restrict__ ef, const int* __restrict__ si,
            const int* __restrict__ ri,
            const float* __restrict__ w0,
            const float* __restrict__ w1, const float* __restrict__ b1,
            const float* __restrict__ w2, const float* __restrict__ b2) {
    extern __shared__ float smem[];
    float* s_w0e = smem;
    float* s_w1  = smem + 2048;
    float* s_w2  = smem + 6144;
    float* s_b1  = smem + 8192;
    float* s_b2  = smem + 8256;
    float* s_h0  = smem + 8288;

    const int tid = threadIdx.x;
    {
        float4* d4 = (float4*)s_w0e;
        const float4* s4 = (const float4*)(w0 + 128 * 64);   // W0e rows
        for (int i = tid; i < 512; i += 256) d4[i] = s4[i];
        d4 = (float4*)s_w1; s4 = (const float4*)w1;
        for (int i = tid; i < 1024; i += 256) d4[i] = s4[i];
        d4 = (float4*)s_w2; s4 = (const float4*)w2;
        for (int i = tid; i < 512; i += 256) d4[i] = s4[i];
        if (tid < 64) s_b1[tid] = b1[tid];
        if (tid < 32) s_b2[tid] = b2[tid];
    }
    __syncthreads();

    const int stride = gridDim.x * 512;
    for (int base = blockIdx.x * 512; base < NE; base += stride) {
        int e0 = base + tid;
        int e1 = base + 256 + tid;
        bool v0 = e0 < NE, v1 = e1 < NE;
        int ee0 = v0 ? e0 : (NE - 1);
        int ee1 = v1 ? e1 : (NE - 1);
        int s0i = si[ee0], r0i = ri[ee0];
        int s1i = si[ee1], r1i = ri[ee1];

        // ---------- layer 0: gather P[s]+Q[r], then ef@W0e ----------
        u64 acc0[32], acc1[32];
        {
            const ulonglong2* p0 = (const ulonglong2*)(g_P + (size_t)s0i * 64);
            const ulonglong2* q0 = (const ulonglong2*)(g_Q + (size_t)r0i * 64);
            const ulonglong2* p1 = (const ulonglong2*)(g_P + (size_t)s1i * 64);
            const ulonglong2* q1 = (const ulonglong2*)(g_Q + (size_t)r1i * 64);
#pragma unroll
            for (int j = 0; j < 16; j++) {
                ulonglong2 a = p0[j], b = q0[j];
                acc0[2 * j]     = add2(a.x, b.x);
                acc0[2 * j + 1] = add2(a.y, b.y);
                ulonglong2 c = p1[j], d = q1[j];
                acc1[2 * j]     = add2(c.x, d.x);
                acc1[2 * j + 1] = add2(c.y, d.y);
            }
        }
        seg_accum2(ef + (size_t)ee0 * 32, ef + (size_t)ee1 * 32, s_w0e, acc0, acc1);

        // relu -> stage h0 in smem (private columns, no sync needed)
#pragma unroll
        for (int j = 0; j < 32; j++) {
            float a, b;
            unpack2(acc0[j], a, b);
            s_h0[(2 * j) * 512 + tid]           = fmaxf(a, 0.f);
            s_h0[(2 * j + 1) * 512 + tid]       = fmaxf(b, 0.f);
            unpack2(acc1[j], a, b);
            s_h0[(2 * j) * 512 + 256 + tid]     = fmaxf(a, 0.f);
            s_h0[(2 * j + 1) * 512 + 256 + tid] = fmaxf(b, 0.f);
        }

        // ---------- layer 1 ----------
        u64 acc2a[32], acc2b[32];
        {
            const ulonglong2* bp = (const ulonglong2*)s_b1;
#pragma unroll
            for (int j = 0; j < 16; j++) {
                ulonglong2 t = bp[j];
                acc2a[2 * j] = t.x; acc2a[2 * j + 1] = t.y;
                acc2b[2 * j] = t.x; acc2b[2 * j + 1] = t.y;
            }
        }
#pragma unroll 2
        for (int k = 0; k < 64; k++) {
            float xa = s_h0[k * 512 + tid];
            float xb = s_h0[k * 512 + 256 + tid];
            rank1_2(xa, xb, s_w1 + k * 64, acc2a, acc2b);
        }
        // relu -> restage h1
#pragma unroll
        for (int j = 0; j < 32; j++) {
            float a, b;
            unpack2(acc2a[j], a, b);
            s_h0[(2 * j) * 512 + tid]           = fmaxf(a, 0.f);
            s_h0[(2 * j + 1) * 512 + tid]       = fmaxf(b, 0.f);
            unpack2(acc2b[j], a, b);
            s_h0[(2 * j) * 512 + 256 + tid]     = fmaxf(a, 0.f);
            s_h0[(2 * j + 1) * 512 + 256 + tid] = fmaxf(b, 0.f);
        }

        // ---------- layer 2 ----------
        u64 acc3a[16], acc3b[16];
        {
            const ulonglong2* bp = (const ulonglong2*)s_b2;
#pragma unroll
            for (int j = 0; j < 8; j++) {
                ulonglong2 t = bp[j];
                acc3a[2 * j] = t.x; acc3a[2 * j + 1] = t.y;
                acc3b[2 * j] = t.x; acc3b[2 * j + 1] = t.y;
            }
        }
#pragma unroll 2
        for (int k = 0; k < 64; k++) {
            float xa = s_h0[k * 512 + tid];
            float xb = s_h0[k * 512 + 256 + tid];
            rank1_2h(xa, xb, s_w2 + k * 32, acc3a, acc3b);
        }

        // ---------- epilogue ----------
        if (v0) epilogue(acc3a, h_d, s0i, r0i);
        if (v1) epilogue(acc3b, h_d, s1i, r1i);
    }
}

__global__ void zero_kernel() {
    int i = blockIdx.x * blockDim.x + threadIdx.x;
    if (i < NN * 32 / 4) ((float4*)g_agg)[i] = make_float4(0.f, 0.f, 0.f, 0.f);
}

// out[n] = h_d_prev[n] + agg[n] @ W
__global__ void final_kernel(const float* __restrict__ h_d, const float* __restrict__ W,
                             float* __restrict__ out) {
    __shared__ float sW[1024];
    int tid = threadIdx.x;
    for (int i = tid; i < 1024; i += 256) sW[i] = W[i];
    __syncthreads();
    int n = blockIdx.x * 8 + (tid >> 5);
    if (n >= NN) return;
    int lane = tid & 31;
    float a = g_agg[(size_t)n * 32 + lane];
    float acc = h_d[(size_t)n * 32 + lane];
#pragma unroll
    for (int k = 0; k < 32; k++) {
        float ak = __shfl_sync(0xffffffffu, a, k);
        acc = fmaf(ak, sW[k * 32 + lane], acc);
    }
    out[(size_t)n * 32 + lane] = acc;
}

extern "C" void kernel_launch(void* const* d_in, const int* in_sizes, int n_in,
                              void* d_out, int out_size) {
    const float* h_d = (const float*)d_in[0];
    const float* h_s = (const float*)d_in[1];
    const float* ef  = (const float*)d_in[2];
    const int*   si  = (const int*)d_in[3];
    const int*   ri  = (const int*)d_in[4];
    const float* w0  = (const float*)d_in[5];
    const float* b0  = (const float*)d_in[6];
    const float* w1  = (const float*)d_in[7];
    const float* b1  = (const float*)d_in[8];
    const float* w2  = (const float*)d_in[9];
    const float* b2  = (const float*)d_in[10];
    const float* W   = (const float*)d_in[11];
    float* out = (float*)d_out;

    cudaFuncSetAttribute(edge_kernel, cudaFuncAttributeMaxDynamicSharedMemorySize,
                         SMEM_BYTES);

    zero_kernel<<<(NN * 32 / 4 + 255) / 256, 256>>>();
    precompute_kernel<<<(NN + 255) / 256, 256>>>(h_s, h_d, w0, b0);
    edge_kernel<<<148, 256, SMEM_BYTES>>>(h_d, ef, si, ri,
                                          w0, w1, b1, w2, b2);
    final_kernel<<<(NN + 7) / 8, 256>>>(h_d, W, out);
}